// round 15
// baseline (speedup 1.0000x reference)
#include <cuda_runtime.h>
#include <cuda_fp16.h>
#include <cstdint>

// Problem constants (fixed by the dataset)
#define TT 512
#define BB 32
#define NN 64
#define KK 32
#define SAMP_PER_B (TT * NN)                 // 32768 samples per batch element
#define SLICES 32                            // sample-slices per batch
#define SAMP_PER_CTA (SAMP_PER_B / SLICES)   // 1024
#define CHUNK 128
#define NCHUNK (SAMP_PER_CTA / CHUNK)        // 8

// smem tables: 32 rows (modes) x 256B (128 samples x fp16), padded to 272B
// stride (17*16B -> ldmatrix conflict-free). Two (A,B) tables per buffer,
// double buffered.
#define ROW_STRIDE 272
#define TBL_BYTES (32 * ROW_STRIDE)          // 8704
#define BUF_BYTES (2 * TBL_BYTES)            // 17408 (A + B tables)
#define SMEM_BYTES (2 * BUF_BYTES)           // 34816
// epilogue reuse: 4 warp regions of 32 rows x 36 floats
#define EPI_WARP_F 1152                      // 4608 B per warp region

#define NCTA (SLICES * BB)                   // 1024

// Deterministic scratch (no device allocation allowed)
__device__ float g_part[NCTA * 1024];        // 4 MB
__device__ float g_berg[BB];
__device__ float g_upart[NCTA];

__device__ __forceinline__ uint32_t smem_u32(const void* p) {
    uint32_t a;
    asm("{ .reg .u64 t; cvta.to.shared.u64 t, %1; cvt.u32.u64 %0, t; }"
        : "=r"(a) : "l"(p));
    return a;
}

#define LDSM_X4(r0, r1, r2, r3, addr) \
    asm volatile("ldmatrix.sync.aligned.m8n8.x4.shared.b16 {%0,%1,%2,%3}, [%4];" \
                 : "=r"(r0), "=r"(r1), "=r"(r2), "=r"(r3) : "r"(addr))

#define MMA16816F16(d, a, bf) \
    asm volatile("mma.sync.aligned.m16n8k16.row.col.f32.f16.f16.f32 " \
                 "{%0,%1,%2,%3}, {%4,%5,%6,%7}, {%8,%9}, {%0,%1,%2,%3};" \
                 : "+f"((d)[0]), "+f"((d)[1]), "+f"((d)[2]), "+f"((d)[3]) \
                 : "r"((a)[0]), "r"((a)[1]), "r"((a)[2]), "r"((a)[3]), \
                   "r"((bf)[0]), "r"((bf)[1]))

#define STS32(addr, v) \
    asm volatile("st.shared.b32 [%0], %1;" :: "r"(addr), "r"(v) : "memory")

// ============================================================================
// Pass 1: warp-level fp16 tensor-core batched GEMM, software-pipelined,
// 1024 CTAs (6/SM resident -> 24 warps/SM of latency hiding).
// CTA = (slice, batch), 4 warps, 32x32 f32 acc per warp, double-buffered
// cos tables: gen(c+1) overlaps MMA(c), ONE sync per chunk.
// Folds a strided |u|^2 partial (512 float4 per CTA) at kernel start.
// ============================================================================
__global__ void __launch_bounds__(128, 6)
pass1_kernel(const float* __restrict__ x, const float* __restrict__ L,
             const float4* __restrict__ u4) {
    __shared__ __align__(16) unsigned char sm[SMEM_BYTES];
    __shared__ float ured[128];

    const int tid   = threadIdx.x;
    const int lane  = tid & 31;
    const int w     = tid >> 5;
    const int slice = blockIdx.x;
    const int b     = blockIdx.y;
    const int cta   = b * SLICES + slice;

    // ---- |u|^2 partial: issue LDGs immediately (overlap with gen(0)) ----
    float usum = 0.0f;
    {
        const float4* up = u4 + (size_t)cta * 512 + tid;
#pragma unroll
        for (int i = 0; i < 4; i++) {
            const float4 v = up[i * 128];
            usum = fmaf(v.x, v.x, usum);
            usum = fmaf(v.y, v.y, usum);
            usum = fmaf(v.z, v.z, usum);
            usum = fmaf(v.w, v.w, usum);
        }
    }

    const uint32_t base = smem_u32(sm);

    // --- generator role: thread t -> dim = t>>6, sample-pair sp = t&63 ---
    const int   gdim = tid >> 6;
    const int   sp   = tid & 63;
    const float invL = 3.14159265358979323846f / __ldg(&L[gdim]);
    const uint32_t gOff = (uint32_t)(gdim * TBL_BYTES + 4 * sp);

    // --- ldmatrix lane addressing (proven mapping), relative to buffer ---
    const int blk = lane >> 3, within = lane & 7;
    const uint32_t aOff0 = (uint32_t)(((blk & 1) * 8 + within) * ROW_STRIDE
                                      + (blk >> 1) * 16);
    const uint32_t bOff0 = (uint32_t)(TBL_BYTES
                                      + ((blk >> 1) * 8 + within) * ROW_STRIDE
                                      + (blk & 1) * 16);

    float acc[2][4][4];
#pragma unroll
    for (int mt = 0; mt < 2; mt++)
#pragma unroll
        for (int nt = 0; nt < 4; nt++)
#pragma unroll
            for (int r = 0; r < 4; r++) acc[mt][nt][r] = 0.0f;

    // ---- generator body (chunk c -> buffer base bufbase) ----
    auto gen = [&](int c, uint32_t bufbase) {
        const int t_idx = slice * 16 + c * 2 + (sp >> 5);
        const int n0    = (2 * sp) & 63;
        const float* xp = x + (((size_t)(t_idx * BB + b)) * NN + n0) * 2 + gdim;
        const float c1a = __cosf(xp[0] * invL);
        const float c1b = __cosf(xp[2] * invL);
        const float c2a = fmaf(c1a + c1a, c1a, -1.0f);   // cos 2theta
        const float c2b = fmaf(c1b + c1b, c1b, -1.0f);
        const float t2a = c2a + c2a, t2b = c2b + c2b;
        float ea0 = 1.0f, ea1 = c2a;
        float eb0 = 1.0f, eb1 = c2b;
        float oa0 = c1a,  oa1 = fmaf(t2a, c1a, -c1a);
        float ob0 = c1b,  ob1 = fmaf(t2b, c1b, -c1b);
        const uint32_t gb = bufbase + gOff;
#pragma unroll
        for (int i = 0; i < 16; i++) {
            uint32_t ep, op;
            asm("cvt.rn.f16x2.f32 %0, %1, %2;" : "=r"(ep) : "f"(eb0), "f"(ea0));
            asm("cvt.rn.f16x2.f32 %0, %1, %2;" : "=r"(op) : "f"(ob0), "f"(oa0));
            STS32(gb + (uint32_t)((2 * i) * ROW_STRIDE), ep);
            STS32(gb + (uint32_t)((2 * i + 1) * ROW_STRIDE), op);
            const float na = fmaf(t2a, ea1, -ea0); ea0 = ea1; ea1 = na;
            const float nb = fmaf(t2b, eb1, -eb0); eb0 = eb1; eb1 = nb;
            const float ma = fmaf(t2a, oa1, -oa0); oa0 = oa1; oa1 = ma;
            const float mb = fmaf(t2b, ob1, -ob0); ob0 = ob1; ob1 = mb;
        }
    };

    gen(0, base);
    __syncthreads();

    for (int c = 0; c < NCHUNK; c++) {
        const uint32_t cur = base + (uint32_t)((c & 1) * BUF_BYTES);
        const uint32_t nxt = base + (uint32_t)(((c + 1) & 1) * BUF_BYTES);

        // ---- consume chunk c: 2 ksteps of 16 samples per warp ----
#pragma unroll
        for (int j = 0; j < 2; j++) {
            const uint32_t kb = (uint32_t)(w * 64 + j * 32);
            uint32_t A[2][4], Bf[4][2];
            LDSM_X4(A[0][0], A[0][1], A[0][2], A[0][3], cur + aOff0 + kb);
            LDSM_X4(A[1][0], A[1][1], A[1][2], A[1][3],
                    cur + aOff0 + (uint32_t)(16 * ROW_STRIDE) + kb);
            LDSM_X4(Bf[0][0], Bf[0][1], Bf[1][0], Bf[1][1], cur + bOff0 + kb);
            LDSM_X4(Bf[2][0], Bf[2][1], Bf[3][0], Bf[3][1],
                    cur + bOff0 + (uint32_t)(16 * ROW_STRIDE) + kb);
#pragma unroll
            for (int mt = 0; mt < 2; mt++)
#pragma unroll
                for (int nt = 0; nt < 4; nt++)
                    MMA16816F16(acc[mt][nt], A[mt], Bf[nt]);
        }

        // ---- generate chunk c+1 into the other buffer ----
        if (c + 1 < NCHUNK) gen(c + 1, nxt);
        __syncthreads();
    }

    // ---- epilogue: warp 32x32 tiles -> smem (reuse table region) ----
    {
        float* eb = (float*)sm + w * EPI_WARP_F;
        const int gID = lane >> 2, tg = lane & 3;
#pragma unroll
        for (int mt = 0; mt < 2; mt++) {
            const int r0 = mt * 16 + gID;
#pragma unroll
            for (int nt = 0; nt < 4; nt++) {
                const int c = nt * 8 + 2 * tg;
                *(float2*)(eb + r0 * 36 + c)       = make_float2(acc[mt][nt][0], acc[mt][nt][1]);
                *(float2*)(eb + (r0 + 8) * 36 + c) = make_float2(acc[mt][nt][2], acc[mt][nt][3]);
            }
        }
        ured[tid] = usum;
    }
    __syncthreads();

    // ---- sum 4 warp tiles, write partial S tile (vectorized) ----
    {
        const float* smf = (const float*)sm;
        const int p  = tid >> 2;
        const int q0 = (tid & 3) * 8;
        float4 s0 = make_float4(0.f, 0.f, 0.f, 0.f);
        float4 s1 = s0;
#pragma unroll
        for (int ww = 0; ww < 4; ww++) {
            const float4* r = (const float4*)(smf + ww * EPI_WARP_F + p * 36 + q0);
            const float4 v0 = r[0], v1 = r[1];
            s0.x += v0.x; s0.y += v0.y; s0.z += v0.z; s0.w += v0.w;
            s1.x += v1.x; s1.y += v1.y; s1.z += v1.z; s1.w += v1.w;
        }
        float4* dst = (float4*)(g_part + (size_t)cta * 1024 + p * 32 + q0);
        dst[0] = s0;
        dst[1] = s1;
    }

    // ---- deterministic CTA reduce of usum -> g_upart[cta] ----
    __syncthreads();
    for (int off = 64; off > 0; off >>= 1) {
        if (tid < off) ured[tid] += ured[tid + off];
        __syncthreads();
    }
    if (tid == 0) g_upart[cta] = ured[0];
}

// ============================================================================
// Mid kernel: per-batch weighted squared-error over modes (32 blocks).
// ============================================================================
__global__ void mid_kernel(const float* __restrict__ cd,
                           const float* __restrict__ nf,
                           const float* __restrict__ nw) {
    const int tid = threadIdx.x;   // 256
    const int b   = blockIdx.x;
    __shared__ float red[256];

    float4 s = make_float4(0.f, 0.f, 0.f, 0.f);
    const float* base = g_part + (size_t)b * SLICES * 1024 + tid * 4;
#pragma unroll
    for (int sl = 0; sl < SLICES; sl++) {
        const float4 v = *(const float4*)(base + sl * 1024);
        s.x += v.x; s.y += v.y; s.z += v.z; s.w += v.w;
    }
    const float4 vnf = *(const float4*)(nf + tid * 4);
    const float4 vcd = *(const float4*)(cd + tid * 4);
    const float4 vnw = *(const float4*)(nw + tid * 4);
    const float inv = 1.0f / (float)SAMP_PER_B;
    const float d0 = s.x * inv / vnf.x - vcd.x;
    const float d1 = s.y * inv / vnf.y - vcd.y;
    const float d2 = s.z * inv / vnf.z - vcd.z;
    const float d3 = s.w * inv / vnf.w - vcd.w;
    red[tid] = d0 * d0 * vnw.x + d1 * d1 * vnw.y
             + d2 * d2 * vnw.z + d3 * d3 * vnw.w;
    __syncthreads();
    for (int off = 128; off > 0; off >>= 1) {
        if (tid < off) red[tid] += red[tid + off];
        __syncthreads();
    }
    if (tid == 0) g_berg[b] = red[0];
}

// ============================================================================
// Final combine: 1024 u-partials + 32 batch terms.
// ============================================================================
__global__ void final_kernel(float* __restrict__ out) {
    const int tid = threadIdx.x;   // 512
    const float UC = 1.0e-3f / (2.0f * (float)SAMP_PER_B * (float)BB);
    float v = (g_upart[tid] + g_upart[tid + 512]) * UC
            + (tid < BB ? g_berg[tid] : 0.0f);
    __shared__ float red[512];
    red[tid] = v;
    __syncthreads();
    for (int off = 256; off > 0; off >>= 1) {
        if (tid < off) red[tid] += red[tid + off];
        __syncthreads();
    }
    if (tid == 0) out[0] = red[0];
}

// ============================================================================
// Launch
// ============================================================================
extern "C" void kernel_launch(void* const* d_in, const int* in_sizes, int n_in,
                              void* d_out, int out_size) {
    const float* x  = (const float*)d_in[0];
    const float* u  = (const float*)d_in[1];
    const float* L  = (const float*)d_in[2];
    const float* cd = (const float*)d_in[3];
    const float* nf = (const float*)d_in[4];
    const float* nw = (const float*)d_in[5];
    float* out = (float*)d_out;

    dim3 grid1(SLICES, BB);               // 32 x 32 = 1024 CTAs
    pass1_kernel<<<grid1, 128>>>(x, L, (const float4*)u);
    mid_kernel<<<BB, 256>>>(cd, nf, nw);
    final_kernel<<<1, 512>>>(out);
}